// round 12
// baseline (speedup 1.0000x reference)
#include <cuda_runtime.h>
#include <cuda_fp16.h>
#include <cstdint>

// LePE windowed attention, sm_103a. 1 CTA = 1 (window, head); 2048 CTAs x 256 thr.
// S=256, hd=32. f16 mma.sync m16n8k16 (fp32 accum) for QK^T and P@V.
// C-frag == A-frag layout trick: no shuffles between softmax and PV.
// R9 fix: conv-weight smem load covered only 256/288 entries (tid<288 with 256
// threads) -> channels 28-31 had garbage LePE weights. Now strided loop.

#define STV 40    // V fp32 row stride (floats)
#define SQH 40    // Q/K f16 row stride (halves); word stride 20 -> conflict-free frags
#define SVT 264   // Vt f16 [d][token] row stride (halves); word stride 132 -> bank=lane

static constexpr int NVF = 256 * STV;
static constexpr int NQH = 256 * SQH;
static constexpr int NVT = 32 * SVT;
static constexpr int SMEM_BYTES = NVF * 4 + (288 + 32) * 4 + (2 * NQH + NVT) * 2;

__device__ __forceinline__ float ex2f(float x) {
    asm("ex2.approx.f32 %0, %0;" : "+f"(x));
    return x;
}
__device__ __forceinline__ void mma16(float c[4], uint32_t a0, uint32_t a1,
                                      uint32_t a2, uint32_t a3,
                                      uint32_t b0, uint32_t b1) {
    asm volatile(
        "mma.sync.aligned.m16n8k16.row.col.f32.f16.f16.f32 "
        "{%0,%1,%2,%3}, {%4,%5,%6,%7}, {%8,%9}, {%0,%1,%2,%3};"
        : "+f"(c[0]), "+f"(c[1]), "+f"(c[2]), "+f"(c[3])
        : "r"(a0), "r"(a1), "r"(a2), "r"(a3), "r"(b0), "r"(b1));
}

__global__ void __launch_bounds__(256, 1)
lepe_attn_kernel(const float* __restrict__ qkv, const float* __restrict__ cw,
                 const float* __restrict__ cb, float* __restrict__ outp) {
    extern __shared__ float sm[];
    float*  Vs = sm;                       // [256][STV] fp32 (LePE conv source)
    float*  Wc = sm + NVF;                 // [32][9]
    float*  Bc = Wc + 288;                 // [32]
    __half* Qh = (__half*)(Bc + 32);       // [256][SQH], pre-scaled by SCALE*log2e
    __half* Kh = Qh + NQH;                 // [256][SQH]
    __half* Vt = Kh + NQH;                 // [32][SVT]  transposed f16 V

    const int tid = threadIdx.x;
    const int h   = blockIdx.x & 7;
    const int w   = blockIdx.x >> 3;
    const int b   = w >> 7;
    const int dz  = (w >> 2) & 31;
    const int nwi = w & 3;

    for (int t = tid; t < 288; t += 256) Wc[t] = cw[h * 288 + t];   // R9 FIX
    if (tid < 32) Bc[tid] = cb[h * 32 + tid];

    const float QSC = 0.17677669529663687f * 1.4426950408889634f; // SCALE*log2e
    const size_t CS = (size_t)16777216;
    const float* base = qkv + (size_t)b * (32768u * 256u) + h * 32;

    #pragma unroll
    for (int it = 0; it < 24; ++it) {
        int i = it * 256 + tid;
        int comp = i >> 11;            // uniform within each iteration
        int r = i & 2047;
        int s = r >> 3;
        int d4 = r & 7;
        int l = dz * 1024 + (s >> 3) * 32 + nwi * 8 + (s & 7);
        float4 v = *(const float4*)(base + (size_t)comp * CS + (size_t)l * 256 + d4 * 4);
        if (comp == 0) {
            __half2 h0 = __floats2half2_rn(v.x * QSC, v.y * QSC);
            __half2 h1 = __floats2half2_rn(v.z * QSC, v.w * QSC);
            *(__half2*)(Qh + s * SQH + d4 * 4) = h0;
            *(__half2*)(Qh + s * SQH + d4 * 4 + 2) = h1;
        } else if (comp == 1) {
            __half2 h0 = __floats2half2_rn(v.x, v.y);
            __half2 h1 = __floats2half2_rn(v.z, v.w);
            *(__half2*)(Kh + s * SQH + d4 * 4) = h0;
            *(__half2*)(Kh + s * SQH + d4 * 4 + 2) = h1;
        } else {
            *(float4*)(Vs + s * STV + d4 * 4) = v;
            Vt[(4 * d4 + 0) * SVT + s] = __float2half_rn(v.x);
            Vt[(4 * d4 + 1) * SVT + s] = __float2half_rn(v.y);
            Vt[(4 * d4 + 2) * SVT + s] = __float2half_rn(v.z);
            Vt[(4 * d4 + 3) * SVT + s] = __float2half_rn(v.w);
        }
    }
    __syncthreads();

    const int lane = tid & 31;
    const int warp = tid >> 5;
    const int gr = lane >> 2;   // group row (lane/4)
    const int tg = lane & 3;    // thread-in-group

    #pragma unroll 1
    for (int pass = 0; pass < 2; ++pass) {
        const int m0 = pass * 128 + warp * 16;

        // ---- Q A-fragments (f16 m16n8k16), 2 k-chunks of 16 ----
        uint32_t qa[2][4];
        #pragma unroll
        for (int kc = 0; kc < 2; ++kc) {
            const uint32_t* q0 = (const uint32_t*)(Qh + (m0 + gr) * SQH + kc * 16);
            const uint32_t* q1 = (const uint32_t*)(Qh + (m0 + gr + 8) * SQH + kc * 16);
            qa[kc][0] = q0[tg];      // A[gr][2tg,2tg+1]
            qa[kc][1] = q1[tg];      // A[gr+8][..]
            qa[kc][2] = q0[tg + 4];  // A[gr][2tg+8,+9]
            qa[kc][3] = q1[tg + 4];
        }

        // ---- S = Q K^T : 16 x 256 per warp (32 n-tiles of 8) ----
        float sacc[32][4];
        #pragma unroll
        for (int nt = 0; nt < 32; ++nt) {
            sacc[nt][0] = 0.f; sacc[nt][1] = 0.f;
            sacc[nt][2] = 0.f; sacc[nt][3] = 0.f;
        }
        #pragma unroll
        for (int nt = 0; nt < 32; ++nt) {
            const uint32_t* kp = (const uint32_t*)(Kh + (nt * 8 + gr) * SQH);
            #pragma unroll
            for (int kc = 0; kc < 2; ++kc) {
                uint32_t b0 = kp[kc * 8 + tg];      // K[n=gr][2tg,2tg+1]
                uint32_t b1 = kp[kc * 8 + tg + 4];  // K[n=gr][2tg+8,+9]
                mma16(sacc[nt], qa[kc][0], qa[kc][1], qa[kc][2], qa[kc][3], b0, b1);
            }
        }

        // ---- softmax (unnormalized, log2-domain): p = 2^s, pack to f16 in place ----
        float rs0 = 0.f, rs1 = 0.f;
        #pragma unroll
        for (int nt = 0; nt < 32; ++nt) {
            __half2 h0 = __floats2half2_rn(ex2f(sacc[nt][0]), ex2f(sacc[nt][1])); // row gr
            __half2 h1 = __floats2half2_rn(ex2f(sacc[nt][2]), ex2f(sacc[nt][3])); // row gr+8
            float2 f0 = __half22float2(h0);
            float2 f1 = __half22float2(h1);
            rs0 += f0.x + f0.y;
            rs1 += f1.x + f1.y;
            sacc[nt][0] = __uint_as_float(*(uint32_t*)&h0);
            sacc[nt][1] = __uint_as_float(*(uint32_t*)&h1);
        }
        rs0 += __shfl_xor_sync(0xffffffffu, rs0, 1);
        rs0 += __shfl_xor_sync(0xffffffffu, rs0, 2);
        rs1 += __shfl_xor_sync(0xffffffffu, rs1, 1);
        rs1 += __shfl_xor_sync(0xffffffffu, rs1, 2);
        const float inv0 = 1.0f / rs0;
        const float inv1 = 1.0f / rs1;

        // ---- O = P V : 16 x 32 per warp. C-frag == A-frag, no shuffles. ----
        float oacc[4][4];
        #pragma unroll
        for (int i = 0; i < 4; ++i) {
            oacc[i][0] = 0.f; oacc[i][1] = 0.f; oacc[i][2] = 0.f; oacc[i][3] = 0.f;
        }
        #pragma unroll
        for (int j = 0; j < 16; ++j) {           // token chunks of 16
            uint32_t a0 = __float_as_uint(sacc[2 * j][0]);     // P[gr][16j+2tg,+1]
            uint32_t a1 = __float_as_uint(sacc[2 * j][1]);     // P[gr+8][..]
            uint32_t a2 = __float_as_uint(sacc[2 * j + 1][0]); // P[gr][16j+8+2tg,+1]
            uint32_t a3 = __float_as_uint(sacc[2 * j + 1][1]);
            #pragma unroll
            for (int i = 0; i < 4; ++i) {        // d tiles of 8
                const uint32_t* vp = (const uint32_t*)Vt + (8 * i + gr) * (SVT / 2) + 8 * j + tg;
                mma16(oacc[i], a0, a1, a2, a3, vp[0], vp[4]);
            }
        }

        // ---- epilogue: normalize, LePE depthwise 3x3 on fp32 V, store ----
        #pragma unroll
        for (int i = 0; i < 4; ++i) {
            #pragma unroll
            for (int rh = 0; rh < 2; ++rh) {
                const int srow = m0 + gr + rh * 8;
                const float inv = rh ? inv1 : inv0;
                const int y = srow >> 3;
                const int x = srow & 7;
                const int dbase = i * 8 + 2 * tg;
                float res[2];
                #pragma unroll
                for (int cc = 0; cc < 2; ++cc) {
                    const int d = dbase + cc;
                    float acc = Bc[d];
                    #pragma unroll
                    for (int ky = 0; ky < 3; ++ky) {
                        const int yy = y + ky - 1;
                        if ((unsigned)yy < 32u) {
                            #pragma unroll
                            for (int kx = 0; kx < 3; ++kx) {
                                const int xx = x + kx - 1;
                                if ((unsigned)xx < 8u)
                                    acc = fmaf(Wc[d * 9 + ky * 3 + kx],
                                               Vs[(yy * 8 + xx) * STV + d], acc);
                            }
                        }
                    }
                    res[cc] = fmaf(oacc[i][rh * 2 + cc], inv, acc);
                }
                const size_t l0 = (size_t)(dz * 1024 + y * 32 + nwi * 8 + x);
                float2 o2; o2.x = res[0]; o2.y = res[1];
                *(float2*)(outp + ((size_t)b * 32768 + l0) * 256 + h * 32 + dbase) = o2;
            }
        }
    }
}

extern "C" void kernel_launch(void* const* d_in, const int* in_sizes, int n_in,
                              void* d_out, int out_size) {
    const float* qkv = (const float*)d_in[0];
    const float* cw  = (const float*)d_in[1];
    const float* cb  = (const float*)d_in[2];
    (void)in_sizes; (void)n_in; (void)out_size;
    cudaFuncSetAttribute(lepe_attn_kernel,
                         cudaFuncAttributeMaxDynamicSharedMemorySize, SMEM_BYTES);
    lepe_attn_kernel<<<2048, 256, SMEM_BYTES>>>(qkv, cw, cb, (float*)d_out);
}

// round 15
// speedup vs baseline: 1.3100x; 1.3100x over previous
#include <cuda_runtime.h>
#include <cuda_fp16.h>
#include <cstdint>

// LePE windowed attention, sm_103a. 1 CTA = 1 (window, head); 2048 CTAs x 256 thr.
// R12: single-pass M=32/warp streaming mainloop (K/V smem traffic halved),
// h2exp2 softmax + MMA-based rowsum (ones B-vector), conv epilogue float2 with
// conflict-optimal STV=44 and hoisted weights, 2 CTAs/SM.

#define STV 44    // V fp32 row stride; 44%32=12 -> conv float2 banks: each bank exactly 2
#define SQH 40    // Q/K f16 row stride (halves); word stride 20 -> conflict-free frags
#define SVT 264   // Vt f16 [d][token] row stride (halves); word stride 132 -> bank=lane

static constexpr int NVF = 256 * STV;     // 11264 floats
static constexpr int NQH = 256 * SQH;     // 10240 halves
static constexpr int NVT = 32 * SVT;      // 8448 halves
static constexpr int SMEM_BYTES = NVF * 4 + (288 + 32) * 4 + (2 * NQH + NVT) * 2; // 104192

__device__ __forceinline__ void mma16(float c[4], uint32_t a0, uint32_t a1,
                                      uint32_t a2, uint32_t a3,
                                      uint32_t b0, uint32_t b1) {
    asm volatile(
        "mma.sync.aligned.m16n8k16.row.col.f32.f16.f16.f32 "
        "{%0,%1,%2,%3}, {%4,%5,%6,%7}, {%8,%9}, {%0,%1,%2,%3};"
        : "+f"(c[0]), "+f"(c[1]), "+f"(c[2]), "+f"(c[3])
        : "r"(a0), "r"(a1), "r"(a2), "r"(a3), "r"(b0), "r"(b1));
}
__device__ __forceinline__ uint32_t exp2pack(float a, float b) {
    __half2 h = h2exp2(__floats2half2_rn(a, b));
    return *(uint32_t*)&h;
}

__global__ void __launch_bounds__(256, 2)
lepe_attn_kernel(const float* __restrict__ qkv, const float* __restrict__ cw,
                 const float* __restrict__ cb, float* __restrict__ outp) {
    extern __shared__ float sm[];
    float*  Vs = sm;                       // [256][STV] fp32 (LePE conv source)
    float*  Wc = sm + NVF;                 // [32][9]
    float*  Bc = Wc + 288;                 // [32]
    __half* Qh = (__half*)(Bc + 32);       // [256][SQH], pre-scaled by SCALE*log2e
    __half* Kh = Qh + NQH;                 // [256][SQH]
    __half* Vt = Kh + NQH;                 // [32][SVT]  transposed f16 V

    const int tid = threadIdx.x;
    const int h   = blockIdx.x & 7;
    const int w   = blockIdx.x >> 3;
    const int b   = w >> 7;
    const int dz  = (w >> 2) & 31;
    const int nwi = w & 3;

    for (int t = tid; t < 288; t += 256) Wc[t] = cw[h * 288 + t];
    if (tid < 32) Bc[tid] = cb[h * 32 + tid];

    const float QSC = 0.17677669529663687f * 1.4426950408889634f; // SCALE*log2e
    const size_t CS = (size_t)16777216;
    const float* base = qkv + (size_t)b * (32768u * 256u) + h * 32;

    #pragma unroll
    for (int it = 0; it < 24; ++it) {
        int i = it * 256 + tid;
        int comp = i >> 11;            // uniform within each iteration
        int r = i & 2047;
        int s = r >> 3;
        int d4 = r & 7;
        int l = dz * 1024 + (s >> 3) * 32 + nwi * 8 + (s & 7);
        float4 v = *(const float4*)(base + (size_t)comp * CS + (size_t)l * 256 + d4 * 4);
        if (comp == 0) {
            __half2 h0 = __floats2half2_rn(v.x * QSC, v.y * QSC);
            __half2 h1 = __floats2half2_rn(v.z * QSC, v.w * QSC);
            *(__half2*)(Qh + s * SQH + d4 * 4) = h0;
            *(__half2*)(Qh + s * SQH + d4 * 4 + 2) = h1;
        } else if (comp == 1) {
            __half2 h0 = __floats2half2_rn(v.x, v.y);
            __half2 h1 = __floats2half2_rn(v.z, v.w);
            *(__half2*)(Kh + s * SQH + d4 * 4) = h0;
            *(__half2*)(Kh + s * SQH + d4 * 4 + 2) = h1;
        } else {
            *(float4*)(Vs + s * STV + d4 * 4) = v;
            Vt[(4 * d4 + 0) * SVT + s] = __float2half_rn(v.x);
            Vt[(4 * d4 + 1) * SVT + s] = __float2half_rn(v.y);
            Vt[(4 * d4 + 2) * SVT + s] = __float2half_rn(v.z);
            Vt[(4 * d4 + 3) * SVT + s] = __float2half_rn(v.w);
        }
    }
    __syncthreads();

    const int lane = tid & 31;
    const int warp = tid >> 5;
    const int gr = lane >> 2;   // group row (lane/4)
    const int tg = lane & 3;    // thread-in-group
    const int m0 = warp * 32;   // this warp's 32 query rows (single pass)
    const uint32_t ONES = 0x3C003C00u;  // half2(1,1)

    // ---- Q A-fragments: [mt][kc][4] ----
    uint32_t qa[2][2][4];
    #pragma unroll
    for (int mt = 0; mt < 2; ++mt) {
        #pragma unroll
        for (int kc = 0; kc < 2; ++kc) {
            const uint32_t* q0 = (const uint32_t*)(Qh + (m0 + 16 * mt + gr) * SQH + kc * 16);
            const uint32_t* q1 = (const uint32_t*)(Qh + (m0 + 16 * mt + gr + 8) * SQH + kc * 16);
            qa[mt][kc][0] = q0[tg];
            qa[mt][kc][1] = q1[tg];
            qa[mt][kc][2] = q0[tg + 4];
            qa[mt][kc][3] = q1[tg + 4];
        }
    }

    float oacc[2][4][4];
    float rsacc[2][4];
    #pragma unroll
    for (int mt = 0; mt < 2; ++mt) {
        #pragma unroll
        for (int i = 0; i < 4; ++i) {
            oacc[mt][i][0] = 0.f; oacc[mt][i][1] = 0.f;
            oacc[mt][i][2] = 0.f; oacc[mt][i][3] = 0.f;
        }
        rsacc[mt][0] = 0.f; rsacc[mt][1] = 0.f;
        rsacc[mt][2] = 0.f; rsacc[mt][3] = 0.f;
    }

    const uint32_t* Khw = (const uint32_t*)Kh;
    const uint32_t* Vtw = (const uint32_t*)Vt;

    #pragma unroll 1
    for (int ch = 0; ch < 8; ++ch) {         // 32 keys per chunk
        // ---- S chunk: QK^T for 4 n-tiles ----
        float sacc[2][4][4];
        #pragma unroll
        for (int mt = 0; mt < 2; ++mt)
            #pragma unroll
            for (int nt = 0; nt < 4; ++nt) {
                sacc[mt][nt][0] = 0.f; sacc[mt][nt][1] = 0.f;
                sacc[mt][nt][2] = 0.f; sacc[mt][nt][3] = 0.f;
            }
        #pragma unroll
        for (int nt = 0; nt < 4; ++nt) {
            const uint32_t* kp = Khw + ((ch * 4 + nt) * 8 + gr) * (SQH / 2);
            #pragma unroll
            for (int kc = 0; kc < 2; ++kc) {
                uint32_t b0 = kp[kc * 8 + tg];
                uint32_t b1 = kp[kc * 8 + tg + 4];
                mma16(sacc[0][nt], qa[0][kc][0], qa[0][kc][1], qa[0][kc][2], qa[0][kc][3], b0, b1);
                mma16(sacc[1][nt], qa[1][kc][0], qa[1][kc][1], qa[1][kc][2], qa[1][kc][3], b0, b1);
            }
        }

        // ---- softmax: p = 2^s in f16x2 (logits pre-scaled by log2e) ----
        uint32_t ph[2][4][2];
        #pragma unroll
        for (int mt = 0; mt < 2; ++mt)
            #pragma unroll
            for (int nt = 0; nt < 4; ++nt) {
                ph[mt][nt][0] = exp2pack(sacc[mt][nt][0], sacc[mt][nt][1]); // row gr
                ph[mt][nt][1] = exp2pack(sacc[mt][nt][2], sacc[mt][nt][3]); // row gr+8
            }

        // ---- rowsum via MMA against ones (fp32 accum, matches f16 P exactly) ----
        #pragma unroll
        for (int mt = 0; mt < 2; ++mt)
            #pragma unroll
            for (int jj = 0; jj < 2; ++jj)
                mma16(rsacc[mt], ph[mt][2 * jj][0], ph[mt][2 * jj][1],
                      ph[mt][2 * jj + 1][0], ph[mt][2 * jj + 1][1], ONES, ONES);

        // ---- O += P V ----
        #pragma unroll
        for (int jj = 0; jj < 2; ++jj) {
            #pragma unroll
            for (int i = 0; i < 4; ++i) {
                const uint32_t* vp = Vtw + (8 * i + gr) * (SVT / 2) + 8 * (2 * ch + jj) + tg;
                uint32_t b0 = vp[0];
                uint32_t b1 = vp[4];
                mma16(oacc[0][i], ph[0][2 * jj][0], ph[0][2 * jj][1],
                      ph[0][2 * jj + 1][0], ph[0][2 * jj + 1][1], b0, b1);
                mma16(oacc[1][i], ph[1][2 * jj][0], ph[1][2 * jj][1],
                      ph[1][2 * jj + 1][0], ph[1][2 * jj + 1][1], b0, b1);
            }
        }
    }

    // ---- epilogue: normalize, LePE depthwise 3x3 on fp32 V (float2 reads,
    //      bank-optimal with STV=44), weights hoisted, store ----
    #pragma unroll
    for (int i = 0; i < 4; ++i) {
        const int dbase = i * 8 + 2 * tg;
        float wv0[9], wv1[9];
        #pragma unroll
        for (int k = 0; k < 9; ++k) {
            wv0[k] = Wc[dbase * 9 + k];
            wv1[k] = Wc[dbase * 9 + 9 + k];
        }
        const float bias0 = Bc[dbase];
        const float bias1 = Bc[dbase + 1];
        #pragma unroll
        for (int mt = 0; mt < 2; ++mt) {
            #pragma unroll
            for (int rh = 0; rh < 2; ++rh) {
                const int srow = m0 + 16 * mt + 8 * rh + gr;
                const float inv = 1.0f / rsacc[mt][2 * rh];
                const int y = srow >> 3;
                const int x = srow & 7;
                float acc0 = bias0, acc1 = bias1;
                #pragma unroll
                for (int ky = 0; ky < 3; ++ky) {
                    const int yy = y + ky - 1;
                    if ((unsigned)yy < 32u) {
                        #pragma unroll
                        for (int kx = 0; kx < 3; ++kx) {
                            const int xx = x + kx - 1;
                            if ((unsigned)xx < 8u) {
                                float2 vv = *(const float2*)(Vs + (yy * 8 + xx) * STV + dbase);
                                acc0 = fmaf(wv0[ky * 3 + kx], vv.x, acc0);
                                acc1 = fmaf(wv1[ky * 3 + kx], vv.y, acc1);
                            }
                        }
                    }
                }
                float2 o2;
                o2.x = fmaf(oacc[mt][i][2 * rh + 0], inv, acc0);
                o2.y = fmaf(oacc[mt][i][2 * rh + 1], inv, acc1);
                const size_t l0 = (size_t)(dz * 1024 + y * 32 + nwi * 8 + x);
                *(float2*)(outp + ((size_t)b * 32768 + l0) * 256 + h * 32 + dbase) = o2;
            }
        }
    }
}

extern "C" void kernel_launch(void* const* d_in, const int* in_sizes, int n_in,
                              void* d_out, int out_size) {
    const float* qkv = (const float*)d_in[0];
    const float* cw  = (const float*)d_in[1];
    const float* cb  = (const float*)d_in[2];
    (void)in_sizes; (void)n_in; (void)out_size;
    cudaFuncSetAttribute(lepe_attn_kernel,
                         cudaFuncAttributeMaxDynamicSharedMemorySize, SMEM_BYTES);
    lepe_attn_kernel<<<2048, 256, SMEM_BYTES>>>(qkv, cw, cb, (float*)d_out);
}